// round 3
// baseline (speedup 1.0000x reference)
#include <cuda_runtime.h>

// RoiAlign (TF crop_and_resize, bilinear), fixed problem shape:
//   features: [B=2, H=64, W=64, C=256] fp32
//   rois:     [B=2, N=2000, 4] fp32 normalized (y1,x1,y2,x2)
//   out:      [B, N, 7, 7, C] fp32
constexpr int H = 64;
constexpr int W = 64;
constexpr int C = 256;
constexpr int PH = 7;
constexpr int PW = 7;
constexpr int CV = C / 4;  // float4 groups per pixel = 64

__global__ void __launch_bounds__(256) roialign_kernel(
    const float4* __restrict__ feat,   // [B, H, W, CV] as float4
    const float*  __restrict__ rois,   // [B, N, 4]
    float4*       __restrict__ out,    // [B, N, PH, PW, CV] as float4
    int N, int total)
{
    int tid = blockIdx.x * blockDim.x + threadIdx.x;
    if (tid >= total) return;

    // tid layout == output layout: (((b*N+n)*PH+py)*PW+px)*CV + c4
    int c4   = tid & (CV - 1);
    int rest = tid >> 6;          // CV = 64
    int px   = rest % PW; rest /= PW;
    int py   = rest % PH; rest /= PH;
    int n    = rest % N;
    int b    = rest / N;

    const float* box = rois + ((size_t)b * N + n) * 4;
    float by1 = box[0];
    float bx1 = box[1];
    float by2 = box[2];
    float bx2 = box[3];

    float fy = (float)py / (float)(PH - 1);
    float fx = (float)px / (float)(PW - 1);
    float ys = (by1 + fy * (by2 - by1)) * (float)(H - 1);
    float xs = (bx1 + fx * (bx2 - bx1)) * (float)(W - 1);

    float y0f = fminf(fmaxf(floorf(ys), 0.0f), (float)(H - 1));
    float x0f = fminf(fmaxf(floorf(xs), 0.0f), (float)(W - 1));
    int y0 = (int)y0f;
    int x0 = (int)x0f;
    int y1i = min(y0 + 1, H - 1);
    int x1i = min(x0 + 1, W - 1);
    float wy = ys - y0f;
    float wx = xs - x0f;

    const float4* fb = feat + (size_t)b * H * W * CV;
    float4 f00 = fb[(y0  * W + x0 ) * CV + c4];
    float4 f01 = fb[(y0  * W + x1i) * CV + c4];
    float4 f10 = fb[(y1i * W + x0 ) * CV + c4];
    float4 f11 = fb[(y1i * W + x1i) * CV + c4];

    float4 r;
    {
        float top, bot;
        top = f00.x + (f01.x - f00.x) * wx;
        bot = f10.x + (f11.x - f10.x) * wx;
        r.x = top + (bot - top) * wy;
        top = f00.y + (f01.y - f00.y) * wx;
        bot = f10.y + (f11.y - f10.y) * wx;
        r.y = top + (bot - top) * wy;
        top = f00.z + (f01.z - f00.z) * wx;
        bot = f10.z + (f11.z - f10.z) * wx;
        r.z = top + (bot - top) * wy;
        top = f00.w + (f01.w - f00.w) * wx;
        bot = f10.w + (f11.w - f10.w) * wx;
        r.w = top + (bot - top) * wy;
    }

    out[tid] = r;
}

extern "C" void kernel_launch(void* const* d_in, const int* in_sizes, int n_in,
                              void* d_out, int out_size)
{
    const float* features = (const float*)d_in[0];
    const float* rois     = (const float*)d_in[1];
    float* out            = (float*)d_out;

    const int B = 2;
    int N = in_sizes[1] / (B * 4);               // 2000
    int total = B * N * PH * PW * CV;            // float4 work items

    int block = 256;
    int grid = (total + block - 1) / block;
    roialign_kernel<<<grid, block>>>(
        (const float4*)features, rois, (float4*)out, N, total);
}

// round 4
// speedup vs baseline: 1.4520x; 1.4520x over previous
#include <cuda_runtime.h>

// RoiAlign (TF crop_and_resize, bilinear), fixed problem shape:
//   features: [B=2, H=64, W=64, C=256] fp32
//   rois:     [B=2, N=2000, 4] fp32 normalized (y1,x1,y2,x2)
//   out:      [B, N, 7, 7, C] fp32
constexpr int H  = 64;
constexpr int W  = 64;
constexpr int C  = 256;
constexpr int PH = 7;
constexpr int PW = 7;
constexpr int CV = C / 4;   // 64 float4 per pixel

// grid = (PH, N, B), block = (32, PW).
// One warp handles one output pixel (b, n, py, px): lane covers c4 = lane
// and c4 = lane + 32 (two float4 = 8 channels per thread).
__global__ void __launch_bounds__(32 * PW) roialign_kernel(
    const float4* __restrict__ feat,   // [B, H, W, CV]
    const float4* __restrict__ rois,   // [B*N] boxes as float4
    float4*       __restrict__ out,    // [B, N, PH, PW, CV]
    int N)
{
    const int py   = blockIdx.x;     // 0..6
    const int n    = blockIdx.y;     // 0..N-1
    const int b    = blockIdx.z;     // 0..1
    const int px   = threadIdx.y;    // 0..6
    const int lane = threadIdx.x;    // 0..31

    // Box (uniform per block row; single 16B load, broadcast)
    float4 box = rois[(size_t)b * N + n];   // (y1, x1, y2, x2)

    float fy = (float)py / (float)(PH - 1);
    float fx = (float)px / (float)(PW - 1);
    float ys = (box.x + fy * (box.z - box.x)) * (float)(H - 1);
    float xs = (box.y + fx * (box.w - box.y)) * (float)(W - 1);

    float y0f = fminf(fmaxf(floorf(ys), 0.0f), (float)(H - 1));
    float x0f = fminf(fmaxf(floorf(xs), 0.0f), (float)(W - 1));
    int   y0  = (int)y0f;
    int   x0  = (int)x0f;
    int   dy  = (y0 + 1 <= H - 1) ? W * CV : 0;   // row step (or clamp)
    int   dx  = (x0 + 1 <= W - 1) ? CV : 0;       // col step (or clamp)

    float wy  = ys - y0f;
    float wx  = xs - x0f;
    float oy  = 1.0f - wy;
    float ox  = 1.0f - wx;
    float w00 = oy * ox;
    float w01 = oy * wx;
    float w10 = wy * ox;
    float w11 = wy * wx;

    const float4* p00 = feat + ((size_t)b * H * W + y0 * W + x0) * CV + lane;

    // 8 independent loads, front-batched for MLP; +32 variants are
    // immediate-offset loads off the same address registers.
    float4 f00a = p00[0];
    float4 f01a = p00[dx];
    float4 f10a = p00[dy];
    float4 f11a = p00[dy + dx];
    float4 f00b = p00[32];
    float4 f01b = p00[dx + 32];
    float4 f10b = p00[dy + 32];
    float4 f11b = p00[dy + dx + 32];

    float4 ra, rb;
    ra.x = fmaf(f11a.x, w11, fmaf(f10a.x, w10, fmaf(f01a.x, w01, f00a.x * w00)));
    ra.y = fmaf(f11a.y, w11, fmaf(f10a.y, w10, fmaf(f01a.y, w01, f00a.y * w00)));
    ra.z = fmaf(f11a.z, w11, fmaf(f10a.z, w10, fmaf(f01a.z, w01, f00a.z * w00)));
    ra.w = fmaf(f11a.w, w11, fmaf(f10a.w, w10, fmaf(f01a.w, w01, f00a.w * w00)));
    rb.x = fmaf(f11b.x, w11, fmaf(f10b.x, w10, fmaf(f01b.x, w01, f00b.x * w00)));
    rb.y = fmaf(f11b.y, w11, fmaf(f10b.y, w10, fmaf(f01b.y, w01, f00b.y * w00)));
    rb.z = fmaf(f11b.z, w11, fmaf(f10b.z, w10, fmaf(f01b.z, w01, f00b.z * w00)));
    rb.w = fmaf(f11b.w, w11, fmaf(f10b.w, w10, fmaf(f01b.w, w01, f00b.w * w00)));

    float4* o = out + ((((size_t)b * N + n) * PH + py) * PW + px) * CV + lane;
    o[0]  = ra;
    o[32] = rb;
}

extern "C" void kernel_launch(void* const* d_in, const int* in_sizes, int n_in,
                              void* d_out, int out_size)
{
    const float4* features = (const float4*)d_in[0];
    const float4* rois     = (const float4*)d_in[1];
    float4* out            = (float4*)d_out;

    const int B = 2;
    int N = in_sizes[1] / (B * 4);     // 2000

    dim3 grid(PH, N, B);
    dim3 block(32, PW);
    roialign_kernel<<<grid, block>>>(features, rois, out, N);
}